// round 14
// baseline (speedup 1.0000x reference)
#include <cuda_runtime.h>
#include <cuda_bf16.h>
#include <cstdint>
#include <cstddef>

#define NN   8192
#define HID  192
#define INF  256
#define MAXN 128

__device__ float g_supA[NN * HID];
__device__ float g_supB[NN * HID];
__device__ float g_featbuf[NN * HID];
__device__ float g_sup3[NN * 3];
__device__ __nv_bfloat16 g_xhi[NN * INF];
__device__ __nv_bfloat16 g_xlo[NN * INF];
#define WT_TOTAL (192*256 + 12*192*192)
__device__ __nv_bfloat16 g_wthi[WT_TOTAL];
__device__ __nv_bfloat16 g_wtlo[WT_TOTAL];
__device__ int   g_nidx[NN * MAXN];
__device__ float g_nval[NN * MAXN];
__device__ int   g_ncnt[NN];

__device__ __forceinline__ uint32_t smem_u32(const void* p) {
    uint32_t a;
    asm("{ .reg .u64 t; cvta.to.shared.u64 t, %1; cvt.u32.u64 %0, t; }" : "=r"(a) : "l"(p));
    return a;
}
__device__ __forceinline__ void cp16(uint32_t d, const void* s) {
    asm volatile("cp.async.cg.shared.global [%0], [%1], 16;" :: "r"(d), "l"(s));
}
__device__ __forceinline__ void cp_commit() { asm volatile("cp.async.commit_group;" ::: "memory"); }
template <int N> __device__ __forceinline__ void cp_wait() {
    asm volatile("cp.async.wait_group %0;" :: "n"(N) : "memory");
}
__device__ __forceinline__ void ldmx4(uint32_t* r, uint32_t a) {
    asm volatile("ldmatrix.sync.aligned.m8n8.x4.shared.b16 {%0,%1,%2,%3}, [%4];"
        : "=r"(r[0]), "=r"(r[1]), "=r"(r[2]), "=r"(r[3]) : "r"(a));
}
__device__ __forceinline__ void mma16816(float* d, const uint32_t* a, const uint32_t* b) {
    asm volatile("mma.sync.aligned.m16n8k16.row.col.f32.bf16.bf16.f32 "
        "{%0,%1,%2,%3}, {%4,%5,%6,%7}, {%8,%9}, {%0,%1,%2,%3};"
        : "+f"(d[0]), "+f"(d[1]), "+f"(d[2]), "+f"(d[3])
        : "r"(a[0]), "r"(a[1]), "r"(a[2]), "r"(a[3]), "r"(b[0]), "r"(b[1]));
}
__device__ __forceinline__ void gdc_launch() { asm volatile("griddepcontrol.launch_dependents;"); }
__device__ __forceinline__ void gdc_wait()   { asm volatile("griddepcontrol.wait;" ::: "memory"); }

__device__ __forceinline__ void split_store4(float t0, float t1, float t2, float t3,
                                             __nv_bfloat16* ohi, __nv_bfloat16* olo, size_t idx)
{
    __nv_bfloat16 h0 = __float2bfloat16(t0), h1 = __float2bfloat16(t1);
    __nv_bfloat16 h2 = __float2bfloat16(t2), h3 = __float2bfloat16(t3);
    __nv_bfloat162 a; a.x = h0; a.y = h1;
    __nv_bfloat162 b; b.x = h2; b.y = h3;
    *reinterpret_cast<__nv_bfloat162*>(ohi + idx)     = a;
    *reinterpret_cast<__nv_bfloat162*>(ohi + idx + 2) = b;
    __nv_bfloat162 c, d;
    c.x = __float2bfloat16(t0 - __bfloat162float(h0));
    c.y = __float2bfloat16(t1 - __bfloat162float(h1));
    d.x = __float2bfloat16(t2 - __bfloat162float(h2));
    d.y = __float2bfloat16(t3 - __bfloat162float(h3));
    *reinterpret_cast<__nv_bfloat162*>(olo + idx)     = c;
    *reinterpret_cast<__nv_bfloat162*>(olo + idx + 2) = d;
}

// ---------------- CSR extraction (pads each row to multiple of 8) ----------------
__global__ __launch_bounds__(256) void build_csr(const float* __restrict__ adj,
                                                 int* __restrict__ nidx,
                                                 float* __restrict__ nval,
                                                 int* __restrict__ ncnt)
{
    int warp = (blockIdx.x * blockDim.x + threadIdx.x) >> 5;
    int lane = threadIdx.x & 31;
    const float4* row = reinterpret_cast<const float4*>(adj + (size_t)warp * NN);
    int* my_idx = nidx + (size_t)warp * MAXN;
    float* my_val = nval + (size_t)warp * MAXN;
    int count = 0;
    for (int it = 0; it < NN / 128; it++) {
        float4 v = row[it * 32 + lane];
        int c0 = it * 128 + lane * 4;
        int my = (v.x != 0.f) + (v.y != 0.f) + (v.z != 0.f) + (v.w != 0.f);
        int inc = my;
        #pragma unroll
        for (int d = 1; d < 32; d <<= 1) {
            int t = __shfl_up_sync(0xffffffffu, inc, d);
            if (lane >= d) inc += t;
        }
        int total = __shfl_sync(0xffffffffu, inc, 31);
        int pos = count + inc - my;
        if (v.x != 0.f) { if (pos < MAXN) { my_idx[pos] = c0;     my_val[pos] = v.x; } pos++; }
        if (v.y != 0.f) { if (pos < MAXN) { my_idx[pos] = c0 + 1; my_val[pos] = v.y; } pos++; }
        if (v.z != 0.f) { if (pos < MAXN) { my_idx[pos] = c0 + 2; my_val[pos] = v.z; } pos++; }
        if (v.w != 0.f) { if (pos < MAXN) { my_idx[pos] = c0 + 3; my_val[pos] = v.w; } pos++; }
        count += total;
    }
    if (count > MAXN) count = MAXN;
    int padded = (count + 7) & ~7;
    if (padded > MAXN) padded = MAXN;
    for (int s = count + lane; s < padded; s += 32) { my_idx[s] = 0; my_val[s] = 0.f; }
    if (lane == 0) ncnt[warp] = padded;
    gdc_launch();
}

__global__ __launch_bounds__(256) void convert_weights(const float* __restrict__ W1,
                                                       const float* __restrict__ W_mid,
                                                       __nv_bfloat16* __restrict__ whi,
                                                       __nv_bfloat16* __restrict__ wlo)
{
    int idx = blockIdx.x * blockDim.x + threadIdx.x;
    if (idx < WT_TOTAL) {
        float w;
        if (idx < 192 * 256) {
            int n = idx / 256, k = idx % 256;
            w = W1[k * 192 + n];
        } else {
            int rel = idx - 192 * 256;
            int i = rel / (192 * 192), r = rel % (192 * 192);
            int n = r / 192, k = r % 192;
            w = W_mid[(size_t)i * 192 * 192 + k * 192 + n];
        }
        __nv_bfloat16 h = __float2bfloat16(w);
        whi[idx] = h;
        wlo[idx] = __float2bfloat16(w - __bfloat162float(h));
    }
    gdc_launch();
}

__global__ __launch_bounds__(256) void convert_features(const float* __restrict__ f,
                                                        __nv_bfloat16* __restrict__ xhi,
                                                        __nv_bfloat16* __restrict__ xlo)
{
    int idx = blockIdx.x * blockDim.x + threadIdx.x;
    if (idx < NN * INF) {
        float v = f[idx];
        __nv_bfloat16 h = __float2bfloat16(v);
        xhi[idx] = h;
        xlo[idx] = __float2bfloat16(v - __bfloat162float(h));
    }
    gdc_launch();
}

// ---------------- gc1 GEMM: K=256, BM=BN=64; weights pre-wait, launch at END ----------------
#define BM 64
#define BN 64
__global__ void __launch_bounds__(256, 1)
gemm_os(const __nv_bfloat16* __restrict__ Xh, const __nv_bfloat16* __restrict__ Xl,
        const __nv_bfloat16* __restrict__ Wh, const __nv_bfloat16* __restrict__ Wl,
        float* __restrict__ S)
{
    constexpr int KK = 256, ASTR = KK * 2 + 16, SLAB = BM * ASTR;
    extern __shared__ char smem[];
    uint32_t sb = smem_u32(smem);
    const uint32_t sAH = sb, sAL = sb + SLAB, sBH = sb + 2 * SLAB, sBL = sb + 3 * SLAB;
    int tid = threadIdx.x;
    int m0 = blockIdx.x * BM, n0 = blockIdx.y * BN;
    int w = tid >> 5, lane = tid & 31;
    int wm = (w & 3) * 16, wn = (w >> 2) * 32;

    #pragma unroll
    for (int v = tid; v < BM * 32; v += 256) {
        int row = v >> 5, seg = v & 31;
        uint32_t so = row * ASTR + seg * 16;
        size_t gb = (size_t)(n0 + row) * KK + seg * 8;
        cp16(sBH + so, Wh + gb);
        cp16(sBL + so, Wl + gb);
    }
    cp_commit();
    gdc_wait();
    #pragma unroll
    for (int ch = 0; ch < 2; ch++) {
        #pragma unroll
        for (int v = tid; v < BM * 16; v += 256) {
            int row = v >> 4, seg = v & 15;
            uint32_t so = row * ASTR + (ch * 16 + seg) * 16;
            size_t ga = (size_t)(m0 + row) * KK + ch * 128 + seg * 8;
            cp16(sAH + so, Xh + ga);
            cp16(sAL + so, Xl + ga);
        }
        cp_commit();
    }

    float acc[4][4];
    #pragma unroll
    for (int nt = 0; nt < 4; nt++)
        #pragma unroll
        for (int q = 0; q < 4; q++) acc[nt][q] = 0.f;

    uint32_t aoff = (wm + (lane & 15)) * ASTR + (lane >> 4) * 16;
    uint32_t boff0 = (wn + (lane & 7) + ((lane >> 4) << 3)) * ASTR + (((lane >> 3) & 1) * 16);
    uint32_t boff1 = boff0 + 16 * ASTR;

    auto compute_range = [&](int k0, int k1) {
        #pragma unroll
        for (int ks = k0; ks < k1; ks++) {
            uint32_t ko = ks * 32;
            uint32_t ah[4], al[4], bh[2][4], bl[2][4];
            ldmx4(ah, sAH + aoff + ko);
            ldmx4(al, sAL + aoff + ko);
            ldmx4(bh[0], sBH + boff0 + ko);
            ldmx4(bl[0], sBL + boff0 + ko);
            ldmx4(bh[1], sBH + boff1 + ko);
            ldmx4(bl[1], sBL + boff1 + ko);
            #pragma unroll
            for (int nt = 0; nt < 4; nt++) {
                const uint32_t* b2h = &bh[nt >> 1][(nt & 1) * 2];
                const uint32_t* b2l = &bl[nt >> 1][(nt & 1) * 2];
                mma16816(acc[nt], ah, b2h);
                mma16816(acc[nt], ah, b2l);
                mma16816(acc[nt], al, b2h);
            }
        }
    };
    cp_wait<1>(); __syncthreads();
    compute_range(0, 8);
    cp_wait<0>(); __syncthreads();
    compute_range(8, 16);

    int rb = m0 + wm + (lane >> 2);
    int cb = n0 + wn + (lane & 3) * 2;
    #pragma unroll
    for (int nt = 0; nt < 4; nt++) {
        int cc = cb + nt * 8;
        *reinterpret_cast<float2*>(&S[(size_t)rb * HID + cc]) = make_float2(acc[nt][0], acc[nt][1]);
        *reinterpret_cast<float2*>(&S[(size_t)(rb + 8) * HID + cc]) = make_float2(acc[nt][2], acc[nt][3]);
    }
    gdc_launch();
}
#define SMEM_K256 (4 * BM * (256 * 2 + 16))

// ---------------- mid GEMM: BM=64, BN=192, K=192, 512 thr; launch at END ----------------
#define GF_ASTR 400
#define GF_ASLAB (64 * GF_ASTR)
#define GF_BSLAB (192 * GF_ASTR)
#define GF_SMEM (2 * GF_ASLAB + 2 * GF_BSLAB)

__global__ void __launch_bounds__(512, 1)
gemm_full(const __nv_bfloat16* __restrict__ Xh, const __nv_bfloat16* __restrict__ Xl,
          const __nv_bfloat16* __restrict__ Wh, const __nv_bfloat16* __restrict__ Wl,
          float* __restrict__ S)
{
    extern __shared__ char smem[];
    uint32_t sb = smem_u32(smem);
    const uint32_t sAH = sb, sAL = sb + GF_ASLAB;
    const uint32_t sBH = sb + 2 * GF_ASLAB, sBL = sb + 2 * GF_ASLAB + GF_BSLAB;
    int tid = threadIdx.x;
    int m0 = blockIdx.x * 64;
    int w = tid >> 5, lane = tid & 31;
    int wm = (w & 3) * 16, wn = (w >> 2) * 48;

    #pragma unroll
    for (int v = tid; v < 192 * 24; v += 512) {
        int row = v / 24, seg = v % 24;
        uint32_t so = row * GF_ASTR + seg * 16;
        size_t g = (size_t)row * 192 + seg * 8;
        cp16(sBH + so, Wh + g);
        cp16(sBL + so, Wl + g);
    }
    cp_commit();
    gdc_wait();
    #pragma unroll
    for (int ch = 0; ch < 2; ch++) {
        #pragma unroll
        for (int v = tid; v < 64 * 12; v += 512) {
            int row = v / 12, seg = v % 12;
            uint32_t so = row * GF_ASTR + (ch * 12 + seg) * 16;
            size_t g = (size_t)(m0 + row) * 192 + ch * 96 + seg * 8;
            cp16(sAH + so, Xh + g);
            cp16(sAL + so, Xl + g);
        }
        cp_commit();
    }

    float acc[6][4];
    #pragma unroll
    for (int nt = 0; nt < 6; nt++)
        #pragma unroll
        for (int q = 0; q < 4; q++) acc[nt][q] = 0.f;

    uint32_t aoff = (wm + (lane & 15)) * GF_ASTR + (lane >> 4) * 16;
    uint32_t bbase = (wn + (lane & 7) + ((lane >> 4) << 3)) * GF_ASTR + (((lane >> 3) & 1) * 16);

    auto compute_range = [&](int k0, int k1) {
        #pragma unroll
        for (int ks = k0; ks < k1; ks++) {
            uint32_t ko = ks * 32;
            uint32_t ah[4], al[4], bh[3][4], bl[3][4];
            ldmx4(ah, sAH + aoff + ko);
            ldmx4(al, sAL + aoff + ko);
            #pragma unroll
            for (int p = 0; p < 3; p++) {
                uint32_t bo = bbase + p * 16 * GF_ASTR + ko;
                ldmx4(bh[p], sBH + bo);
                ldmx4(bl[p], sBL + bo);
            }
            #pragma unroll
            for (int nt = 0; nt < 6; nt++) {
                const uint32_t* b2h = &bh[nt >> 1][(nt & 1) * 2];
                const uint32_t* b2l = &bl[nt >> 1][(nt & 1) * 2];
                mma16816(acc[nt], ah, b2h);
                mma16816(acc[nt], ah, b2l);
                mma16816(acc[nt], al, b2h);
            }
        }
    };
    cp_wait<1>(); __syncthreads();
    compute_range(0, 6);
    cp_wait<0>(); __syncthreads();
    compute_range(6, 12);

    int rb = m0 + wm + (lane >> 2);
    int cb = wn + (lane & 3) * 2;
    #pragma unroll
    for (int nt = 0; nt < 6; nt++) {
        int cc = cb + nt * 8;
        *reinterpret_cast<float2*>(&S[(size_t)rb * HID + cc]) = make_float2(acc[nt][0], acc[nt][1]);
        *reinterpret_cast<float2*>(&S[(size_t)(rb + 8) * HID + cc]) = make_float2(acc[nt][2], acc[nt][3]);
    }
    gdc_launch();
}

// ---------------- aggregation: TWO warps per row (32 side cols each) ----------------
// warp pair (warp>>1 = row-in-block, warp&1 = column half). Per metadata batch of
// 4 neighbors, one LDG.128 serves 4 neighbor rows (lane>>3 selects neighbor,
// lane&7 selects col quartet); reduce over neighbor groups with shfl_xor 8/16.
template <int MODE>
__global__ __launch_bounds__(256) void agg2(const float* __restrict__ S,
                                            const float* __restrict__ bias,
                                            const float* __restrict__ resptr,
                                            float* __restrict__ fbout,
                                            __nv_bfloat16* __restrict__ ohi,
                                            __nv_bfloat16* __restrict__ olo,
                                            const int* __restrict__ nidx,
                                            const float* __restrict__ nval,
                                            const int* __restrict__ ncnt)
{
    gdc_wait();
    int tid = threadIdx.x;
    int warp = tid >> 5, lane = tid & 31;
    int row = blockIdx.x * 4 + (warp >> 1);
    int colhalf = warp & 1;
    int g = lane >> 3;          // neighbor group 0..3
    int cl = lane & 7;          // col quartet within 32-col half
    int cnt = ncnt[row];
    const int* ni = nidx + (size_t)row * MAXN;
    const float* nv = nval + (size_t)row * MAXN;
    int colbase = colhalf * 32;

    float a0 = 0.f, a1 = 0.f, a2 = 0.f, a3 = 0.f;
    for (int i = 0; i < cnt; i += 4) {
        int4   ji = *reinterpret_cast<const int4*>(ni + i);
        float4 wv = *reinterpret_cast<const float4*>(nv + i);
        int n; float wgt;
        if (g == 0)      { n = ji.x; wgt = wv.x; }
        else if (g == 1) { n = ji.y; wgt = wv.y; }
        else if (g == 2) { n = ji.z; wgt = wv.z; }
        else             { n = ji.w; wgt = wv.w; }
        float4 v = *reinterpret_cast<const float4*>(S + (size_t)n * HID + colbase + 4 * cl);
        a0 = fmaf(wgt, v.x, a0); a1 = fmaf(wgt, v.y, a1);
        a2 = fmaf(wgt, v.z, a2); a3 = fmaf(wgt, v.w, a3);
    }
    // reduce across the 4 neighbor groups (lanes differing in bits 3,4)
    a0 += __shfl_xor_sync(0xffffffffu, a0, 8);  a0 += __shfl_xor_sync(0xffffffffu, a0, 16);
    a1 += __shfl_xor_sync(0xffffffffu, a1, 8);  a1 += __shfl_xor_sync(0xffffffffu, a1, 16);
    a2 += __shfl_xor_sync(0xffffffffu, a2, 8);  a2 += __shfl_xor_sync(0xffffffffu, a2, 16);
    a3 += __shfl_xor_sync(0xffffffffu, a3, 8);  a3 += __shfl_xor_sync(0xffffffffu, a3, 16);

    size_t rbase = (size_t)row * HID;

    // side cols: this warp's 32-col half, lanes 0..7 each own 4 cols
    if (lane < 8) {
        int c = colbase + 4 * lane;
        float4 bs = *reinterpret_cast<const float4*>(bias + c);
        float t0 = fmaxf(a0 + bs.x, 0.f), t1 = fmaxf(a1 + bs.y, 0.f);
        float t2 = fmaxf(a2 + bs.z, 0.f), t3 = fmaxf(a3 + bs.w, 0.f);
        if (MODE == 1) {
            float4 rv = *reinterpret_cast<const float4*>(resptr + (size_t)row * INF + c);
            t0 = (rv.x + t0) * 0.5f; t1 = (rv.y + t1) * 0.5f;
            t2 = (rv.z + t2) * 0.5f; t3 = (rv.w + t3) * 0.5f;
        }
        if (MODE == 2) {
            float4 rv = *reinterpret_cast<const float4*>(resptr + rbase + c);
            t0 = (rv.x + t0) * 0.5f; t1 = (rv.y + t1) * 0.5f;
            t2 = (rv.z + t2) * 0.5f; t3 = (rv.w + t3) * 0.5f;
        }
        if (MODE >= 1)
            *reinterpret_cast<float4*>(fbout + rbase + c) = make_float4(t0, t1, t2, t3);
        split_store4(t0, t1, t2, t3, ohi, olo, rbase + c);
    }

    // passthrough: warp0 -> cols 64..127, warp1 -> cols 128..191 (16 lanes x 4 cols)
    if (lane < 16) {
        int c = 64 + colhalf * 64 + 4 * lane;
        float4 sv = *reinterpret_cast<const float4*>(S + rbase + c);
        float4 bs = *reinterpret_cast<const float4*>(bias + c);
        float t0 = fmaxf(sv.x + bs.x, 0.f), t1 = fmaxf(sv.y + bs.y, 0.f);
        float t2 = fmaxf(sv.z + bs.z, 0.f), t3 = fmaxf(sv.w + bs.w, 0.f);
        if (MODE == 1) {
            float4 rv = *reinterpret_cast<const float4*>(resptr + (size_t)row * INF + c);
            t0 = (rv.x + t0) * 0.5f; t1 = (rv.y + t1) * 0.5f;
            t2 = (rv.z + t2) * 0.5f; t3 = (rv.w + t3) * 0.5f;
        }
        if (MODE == 2) {
            float4 rv = *reinterpret_cast<const float4*>(resptr + rbase + c);
            t0 = (rv.x + t0) * 0.5f; t1 = (rv.y + t1) * 0.5f;
            t2 = (rv.z + t2) * 0.5f; t3 = (rv.w + t3) * 0.5f;
        }
        if (MODE >= 1)
            *reinterpret_cast<float4*>(fbout + rbase + c) = make_float4(t0, t1, t2, t3);
        split_store4(t0, t1, t2, t3, ohi, olo, rbase + c);
    }
    gdc_launch();
}

// ---------------- fused tail (gc13 + feat @ W_out), PDL ----------------
__global__ __launch_bounds__(256) void tail_fused(const float* __restrict__ S,
                                                  const float* __restrict__ bias,
                                                  float* __restrict__ fb,
                                                  float* __restrict__ feat_out,
                                                  const float* __restrict__ W_out,
                                                  float* __restrict__ sup3,
                                                  const int* __restrict__ nidx,
                                                  const float* __restrict__ nval,
                                                  const int* __restrict__ ncnt)
{
    gdc_wait();
    int row = (blockIdx.x * blockDim.x + threadIdx.x) >> 5;
    int lane = threadIdx.x & 31;
    int cnt = ncnt[row];
    const int* ni = nidx + (size_t)row * MAXN;
    const float* nv = nval + (size_t)row * MAXN;
    float acc0 = 0.f, acc1 = 0.f, e0 = 0.f, e1 = 0.f;
    for (int i = 0; i < cnt; i += 4) {
        int4   ji = *reinterpret_cast<const int4*>(ni + i);
        float4 ui = *reinterpret_cast<const float4*>(nv + i);
        const float* s0 = S + (size_t)ji.x * HID;
        const float* s1 = S + (size_t)ji.y * HID;
        const float* s2 = S + (size_t)ji.z * HID;
        const float* s3 = S + (size_t)ji.w * HID;
        acc0 = fmaf(ui.x, s0[lane], acc0);  acc1 = fmaf(ui.x, s0[lane + 32], acc1);
        e0   = fmaf(ui.y, s1[lane], e0);    e1   = fmaf(ui.y, s1[lane + 32], e1);
        acc0 = fmaf(ui.z, s2[lane], acc0);  acc1 = fmaf(ui.z, s2[lane + 32], acc1);
        e0   = fmaf(ui.w, s3[lane], e0);    e1   = fmaf(ui.w, s3[lane + 32], e1);
    }
    acc0 += e0; acc1 += e1;

    float w0s = 0.f, w1s = 0.f, w2s = 0.f;
    size_t rbase = (size_t)row * HID;
    #pragma unroll
    for (int j = 0; j < 6; j++) {
        int c = 32 * j + lane;
        float t = (j == 0) ? acc0 : (j == 1) ? acc1 : S[rbase + c];
        t += bias[c];
        t = fmaxf(t, 0.f);
        t = (fb[rbase + c] + t) * 0.5f;
        fb[rbase + c] = t;
        feat_out[rbase + c] = t;
        w0s = fmaf(t, W_out[c * 3 + 0], w0s);
        w1s = fmaf(t, W_out[c * 3 + 1], w1s);
        w2s = fmaf(t, W_out[c * 3 + 2], w2s);
    }
    #pragma unroll
    for (int d = 16; d; d >>= 1) {
        w0s += __shfl_xor_sync(0xffffffffu, w0s, d);
        w1s += __shfl_xor_sync(0xffffffffu, w1s, d);
        w2s += __shfl_xor_sync(0xffffffffu, w2s, d);
    }
    if (lane == 0) {
        sup3[row * 3 + 0] = w0s;
        sup3[row * 3 + 1] = w1s;
        sup3[row * 3 + 2] = w2s;
    }
    gdc_launch();
}

// ---------------- coords, PDL ----------------
__global__ __launch_bounds__(256) void agg_coords(const float* __restrict__ S,
                                                  const float* __restrict__ bias,
                                                  float* __restrict__ out,
                                                  const int* __restrict__ nidx,
                                                  const float* __restrict__ nval,
                                                  const int* __restrict__ ncnt)
{
    gdc_wait();
    int warp = (blockIdx.x * blockDim.x + threadIdx.x) >> 5;
    int lane = threadIdx.x & 31;
    int cnt = ncnt[warp];
    const int* ni = nidx + (size_t)warp * MAXN;
    const float* nv = nval + (size_t)warp * MAXN;
    float acc0 = 0.f;
    for (int i = 0; i < cnt; i++) {
        if (lane < 2) acc0 = fmaf(nv[i], S[(size_t)ni[i] * 3 + lane], acc0);
    }
    if (lane < 3) {
        float t = (lane < 2) ? acc0 : S[(size_t)warp * 3 + lane];
        out[(size_t)warp * 3 + lane] = t + bias[lane];
    }
}

// ---------------- host PDL launcher ----------------
template <typename F, typename... Args>
static inline void pdl(F fn, dim3 g, dim3 b, size_t sm, Args... args)
{
    cudaLaunchConfig_t cfg = {};
    cfg.gridDim = g; cfg.blockDim = b; cfg.dynamicSmemBytes = sm; cfg.stream = 0;
    cudaLaunchAttribute at;
    at.id = cudaLaunchAttributeProgrammaticStreamSerialization;
    at.val.programmaticStreamSerializationAllowed = 1;
    cfg.attrs = &at; cfg.numAttrs = 1;
    cudaLaunchKernelEx(&cfg, fn, args...);
}

extern "C" void kernel_launch(void* const* d_in, const int* in_sizes, int n_in,
                              void* d_out, int out_size)
{
    const float* features = (const float*)d_in[0];
    const float* adj      = (const float*)d_in[1];
    const float* W1       = (const float*)d_in[2];
    const float* b1       = (const float*)d_in[3];
    const float* W_mid    = (const float*)d_in[4];
    const float* b_mid    = (const float*)d_in[5];
    const float* W_out    = (const float*)d_in[6];
    const float* b_out    = (const float*)d_in[7];
    float* out = (float*)d_out;
    float* coords   = out;
    float* feat_out = out + NN * 3;

    float *sa, *sbuf, *fb, *sup3, *nval;
    __nv_bfloat16 *xhi, *xlo, *whi, *wlo;
    int *nidx, *ncnt;
    cudaGetSymbolAddress((void**)&sa,   g_supA);
    cudaGetSymbolAddress((void**)&sbuf, g_supB);
    cudaGetSymbolAddress((void**)&fb,   g_featbuf);
    cudaGetSymbolAddress((void**)&sup3, g_sup3);
    cudaGetSymbolAddress((void**)&xhi,  g_xhi);
    cudaGetSymbolAddress((void**)&xlo,  g_xlo);
    cudaGetSymbolAddress((void**)&whi,  g_wthi);
    cudaGetSymbolAddress((void**)&wlo,  g_wtlo);
    cudaGetSymbolAddress((void**)&nidx, g_nidx);
    cudaGetSymbolAddress((void**)&nval, g_nval);
    cudaGetSymbolAddress((void**)&ncnt, g_ncnt);

    cudaFuncSetAttribute(gemm_os, cudaFuncAttributeMaxDynamicSharedMemorySize, SMEM_K256);
    cudaFuncSetAttribute(gemm_full, cudaFuncAttributeMaxDynamicSharedMemorySize, GF_SMEM);

    // R7/R10-proven ordering: csr FIRST (its 268MB sweep evicts L2), converts after.
    build_csr<<<NN / 8, 256>>>(adj, nidx, nval, ncnt);
    pdl(convert_weights, dim3((WT_TOTAL + 255) / 256), dim3(256), (size_t)0, W1, W_mid, whi, wlo);
    pdl(convert_features, dim3((NN * INF + 255) / 256), dim3(256), (size_t)0, features, xhi, xlo);

    auto woff = [](int i) { return (size_t)192 * 256 + (size_t)i * 192 * 192; };

    pdl(gemm_os, dim3(NN / BM, HID / BN), dim3(256), (size_t)SMEM_K256,
        (const __nv_bfloat16*)xhi, (const __nv_bfloat16*)xlo,
        (const __nv_bfloat16*)whi, (const __nv_bfloat16*)wlo, sa);

    pdl(agg2<0>, dim3(NN / 4), dim3(256), (size_t)0,
        (const float*)sa, b1, (const float*)nullptr, (float*)nullptr,
        xhi, xlo, (const int*)nidx, (const float*)nval, (const int*)ncnt);
    pdl(gemm_full, dim3(NN / 64), dim3(512), (size_t)GF_SMEM,
        (const __nv_bfloat16*)xhi, (const __nv_bfloat16*)xlo,
        (const __nv_bfloat16*)(whi + woff(0)), (const __nv_bfloat16*)(wlo + woff(0)), sbuf);
    pdl(agg2<1>, dim3(NN / 4), dim3(256), (size_t)0,
        (const float*)sbuf, (const float*)(b_mid + 0), features, fb,
        xhi, xlo, (const int*)nidx, (const float*)nval, (const int*)ncnt);
    pdl(gemm_full, dim3(NN / 64), dim3(512), (size_t)GF_SMEM,
        (const __nv_bfloat16*)xhi, (const __nv_bfloat16*)xlo,
        (const __nv_bfloat16*)(whi + woff(1)), (const __nv_bfloat16*)(wlo + woff(1)), sa);

    float* cur = sa; float* nxt = sbuf;
    for (int p = 0; p < 5; p++) {
        int bi = 1 + 2 * p;
        pdl(agg2<0>, dim3(NN / 4), dim3(256), (size_t)0,
            (const float*)cur, (const float*)(b_mid + (size_t)bi * HID),
            (const float*)nullptr, (float*)nullptr,
            xhi, xlo, (const int*)nidx, (const float*)nval, (const int*)ncnt);
        pdl(gemm_full, dim3(NN / 64), dim3(512), (size_t)GF_SMEM,
            (const __nv_bfloat16*)xhi, (const __nv_bfloat16*)xlo,
            (const __nv_bfloat16*)(whi + woff(bi + 1)), (const __nv_bfloat16*)(wlo + woff(bi + 1)), nxt);
        { float* t = cur; cur = nxt; nxt = t; }
        pdl(agg2<2>, dim3(NN / 4), dim3(256), (size_t)0,
            (const float*)cur, (const float*)(b_mid + (size_t)(bi + 1) * HID),
            (const float*)fb, fb,
            xhi, xlo, (const int*)nidx, (const float*)nval, (const int*)ncnt);
        pdl(gemm_full, dim3(NN / 64), dim3(512), (size_t)GF_SMEM,
            (const __nv_bfloat16*)xhi, (const __nv_bfloat16*)xlo,
            (const __nv_bfloat16*)(whi + woff(bi + 2)), (const __nv_bfloat16*)(wlo + woff(bi + 2)), nxt);
        { float* t = cur; cur = nxt; nxt = t; }
    }

    pdl(tail_fused, dim3(NN / 8), dim3(256), (size_t)0,
        (const float*)cur, (const float*)(b_mid + (size_t)11 * HID), fb, feat_out,
        W_out, sup3, (const int*)nidx, (const float*)nval, (const int*)ncnt);
    pdl(agg_coords, dim3(NN / 8), dim3(256), (size_t)0,
        (const float*)sup3, b_out, coords,
        (const int*)nidx, (const float*)nval, (const int*)ncnt);
}

// round 15
// speedup vs baseline: 1.0151x; 1.0151x over previous
#include <cuda_runtime.h>
#include <cuda_bf16.h>
#include <cstdint>
#include <cstddef>

#define NN   8192
#define HID  192
#define INF  256
#define MAXN 128

__device__ float g_supA[NN * HID];
__device__ float g_supB[NN * HID];
__device__ float g_featbuf[NN * HID];
__device__ float g_sup3[NN * 3];
__device__ __nv_bfloat16 g_xhi[NN * INF];
__device__ __nv_bfloat16 g_xlo[NN * INF];
#define WT_TOTAL (192*256 + 12*192*192)
__device__ __nv_bfloat16 g_wthi[WT_TOTAL];
__device__ __nv_bfloat16 g_wtlo[WT_TOTAL];
__device__ int   g_nidx[NN * MAXN];
__device__ float g_nval[NN * MAXN];
__device__ int   g_ncnt[NN];
__device__ int   g_bar;

__device__ __forceinline__ uint32_t smem_u32(const void* p) {
    uint32_t a;
    asm("{ .reg .u64 t; cvta.to.shared.u64 t, %1; cvt.u32.u64 %0, t; }" : "=r"(a) : "l"(p));
    return a;
}
__device__ __forceinline__ void cp16(uint32_t d, const void* s) {
    asm volatile("cp.async.cg.shared.global [%0], [%1], 16;" :: "r"(d), "l"(s));
}
__device__ __forceinline__ void cp_commit() { asm volatile("cp.async.commit_group;" ::: "memory"); }
template <int N> __device__ __forceinline__ void cp_wait() {
    asm volatile("cp.async.wait_group %0;" :: "n"(N) : "memory");
}
__device__ __forceinline__ void ldmx4(uint32_t* r, uint32_t a) {
    asm volatile("ldmatrix.sync.aligned.m8n8.x4.shared.b16 {%0,%1,%2,%3}, [%4];"
        : "=r"(r[0]), "=r"(r[1]), "=r"(r[2]), "=r"(r[3]) : "r"(a));
}
__device__ __forceinline__ void mma16816(float* d, const uint32_t* a, const uint32_t* b) {
    asm volatile("mma.sync.aligned.m16n8k16.row.col.f32.bf16.bf16.f32 "
        "{%0,%1,%2,%3}, {%4,%5,%6,%7}, {%8,%9}, {%0,%1,%2,%3};"
        : "+f"(d[0]), "+f"(d[1]), "+f"(d[2]), "+f"(d[3])
        : "r"(a[0]), "r"(a[1]), "r"(a[2]), "r"(a[3]), "r"(b[0]), "r"(b[1]));
}
__device__ __forceinline__ void gdc_launch() { asm volatile("griddepcontrol.launch_dependents;"); }
__device__ __forceinline__ void gdc_wait()   { asm volatile("griddepcontrol.wait;" ::: "memory"); }

__device__ __forceinline__ void grid_barrier(int tid) {
    __syncthreads();
    if (tid == 0) {
        __threadfence();
        int old = atomicAdd(&g_bar, 1);
        int target = (old & ~127) + 128;
        while (*((volatile int*)&g_bar) < target) __nanosleep(128);
        __threadfence();
    }
    __syncthreads();
}

__device__ __forceinline__ void split_store4(float t0, float t1, float t2, float t3,
                                             __nv_bfloat16* ohi, __nv_bfloat16* olo, size_t idx)
{
    __nv_bfloat16 h0 = __float2bfloat16(t0), h1 = __float2bfloat16(t1);
    __nv_bfloat16 h2 = __float2bfloat16(t2), h3 = __float2bfloat16(t3);
    __nv_bfloat162 a; a.x = h0; a.y = h1;
    __nv_bfloat162 b; b.x = h2; b.y = h3;
    *reinterpret_cast<__nv_bfloat162*>(ohi + idx)     = a;
    *reinterpret_cast<__nv_bfloat162*>(ohi + idx + 2) = b;
    __nv_bfloat162 c, d;
    c.x = __float2bfloat16(t0 - __bfloat162float(h0));
    c.y = __float2bfloat16(t1 - __bfloat162float(h1));
    d.x = __float2bfloat16(t2 - __bfloat162float(h2));
    d.y = __float2bfloat16(t3 - __bfloat162float(h3));
    *reinterpret_cast<__nv_bfloat162*>(olo + idx)     = c;
    *reinterpret_cast<__nv_bfloat162*>(olo + idx + 2) = d;
}

// smem variant: h at base_h + coff, lo at base_l + coff (byte offsets)
__device__ __forceinline__ void split_store4_smem(float t0, float t1, float t2, float t3,
                                                  char* base_h, char* base_l)
{
    __nv_bfloat16 h0 = __float2bfloat16(t0), h1 = __float2bfloat16(t1);
    __nv_bfloat16 h2 = __float2bfloat16(t2), h3 = __float2bfloat16(t3);
    __nv_bfloat162 a; a.x = h0; a.y = h1;
    __nv_bfloat162 b; b.x = h2; b.y = h3;
    *reinterpret_cast<__nv_bfloat162*>(base_h)     = a;
    *reinterpret_cast<__nv_bfloat162*>(base_h + 4) = b;
    __nv_bfloat162 c, d;
    c.x = __float2bfloat16(t0 - __bfloat162float(h0));
    c.y = __float2bfloat16(t1 - __bfloat162float(h1));
    d.x = __float2bfloat16(t2 - __bfloat162float(h2));
    d.y = __float2bfloat16(t3 - __bfloat162float(h3));
    *reinterpret_cast<__nv_bfloat162*>(base_l)     = c;
    *reinterpret_cast<__nv_bfloat162*>(base_l + 4) = d;
}

// ---------------- CSR extraction (pads each row to multiple of 8) ----------------
__global__ __launch_bounds__(256) void build_csr(const float* __restrict__ adj,
                                                 int* __restrict__ nidx,
                                                 float* __restrict__ nval,
                                                 int* __restrict__ ncnt)
{
    int warp = (blockIdx.x * blockDim.x + threadIdx.x) >> 5;
    int lane = threadIdx.x & 31;
    const float4* row = reinterpret_cast<const float4*>(adj + (size_t)warp * NN);
    int* my_idx = nidx + (size_t)warp * MAXN;
    float* my_val = nval + (size_t)warp * MAXN;
    int count = 0;
    for (int it = 0; it < NN / 128; it++) {
        float4 v = row[it * 32 + lane];
        int c0 = it * 128 + lane * 4;
        int my = (v.x != 0.f) + (v.y != 0.f) + (v.z != 0.f) + (v.w != 0.f);
        int inc = my;
        #pragma unroll
        for (int d = 1; d < 32; d <<= 1) {
            int t = __shfl_up_sync(0xffffffffu, inc, d);
            if (lane >= d) inc += t;
        }
        int total = __shfl_sync(0xffffffffu, inc, 31);
        int pos = count + inc - my;
        if (v.x != 0.f) { if (pos < MAXN) { my_idx[pos] = c0;     my_val[pos] = v.x; } pos++; }
        if (v.y != 0.f) { if (pos < MAXN) { my_idx[pos] = c0 + 1; my_val[pos] = v.y; } pos++; }
        if (v.z != 0.f) { if (pos < MAXN) { my_idx[pos] = c0 + 2; my_val[pos] = v.z; } pos++; }
        if (v.w != 0.f) { if (pos < MAXN) { my_idx[pos] = c0 + 3; my_val[pos] = v.w; } pos++; }
        count += total;
    }
    if (count > MAXN) count = MAXN;
    int padded = (count + 7) & ~7;
    if (padded > MAXN) padded = MAXN;
    for (int s = count + lane; s < padded; s += 32) { my_idx[s] = 0; my_val[s] = 0.f; }
    if (lane == 0) ncnt[warp] = padded;
    gdc_launch();
}

__global__ __launch_bounds__(256) void convert_weights(const float* __restrict__ W1,
                                                       const float* __restrict__ W_mid,
                                                       __nv_bfloat16* __restrict__ whi,
                                                       __nv_bfloat16* __restrict__ wlo)
{
    int idx = blockIdx.x * blockDim.x + threadIdx.x;
    if (idx < WT_TOTAL) {
        float w;
        if (idx < 192 * 256) {
            int n = idx / 256, k = idx % 256;
            w = W1[k * 192 + n];
        } else {
            int rel = idx - 192 * 256;
            int i = rel / (192 * 192), r = rel % (192 * 192);
            int n = r / 192, k = r % 192;
            w = W_mid[(size_t)i * 192 * 192 + k * 192 + n];
        }
        __nv_bfloat16 h = __float2bfloat16(w);
        whi[idx] = h;
        wlo[idx] = __float2bfloat16(w - __bfloat162float(h));
    }
    gdc_launch();
}

__global__ __launch_bounds__(256) void convert_features(const float* __restrict__ f,
                                                        __nv_bfloat16* __restrict__ xhi,
                                                        __nv_bfloat16* __restrict__ xlo)
{
    int idx = blockIdx.x * blockDim.x + threadIdx.x;
    if (idx < NN * INF) {
        float v = f[idx];
        __nv_bfloat16 h = __float2bfloat16(v);
        xhi[idx] = h;
        xlo[idx] = __float2bfloat16(v - __bfloat162float(h));
    }
    gdc_launch();
}

// ---------------- gc1 GEMM: K=256, BM=BN=64 (unchanged, verified) ----------------
#define BM 64
#define BN 64
__global__ void __launch_bounds__(256, 1)
gemm_os(const __nv_bfloat16* __restrict__ Xh, const __nv_bfloat16* __restrict__ Xl,
        const __nv_bfloat16* __restrict__ Wh, const __nv_bfloat16* __restrict__ Wl,
        float* __restrict__ S)
{
    constexpr int KK = 256, ASTR = KK * 2 + 16, SLAB = BM * ASTR;
    extern __shared__ char smem[];
    uint32_t sb = smem_u32(smem);
    const uint32_t sAH = sb, sAL = sb + SLAB, sBH = sb + 2 * SLAB, sBL = sb + 3 * SLAB;
    int tid = threadIdx.x;
    int m0 = blockIdx.x * BM, n0 = blockIdx.y * BN;
    int w = tid >> 5, lane = tid & 31;
    int wm = (w & 3) * 16, wn = (w >> 2) * 32;

    #pragma unroll
    for (int v = tid; v < BM * 32; v += 256) {
        int row = v >> 5, seg = v & 31;
        uint32_t so = row * ASTR + seg * 16;
        size_t gb = (size_t)(n0 + row) * KK + seg * 8;
        cp16(sBH + so, Wh + gb);
        cp16(sBL + so, Wl + gb);
    }
    cp_commit();
    gdc_wait();
    #pragma unroll
    for (int ch = 0; ch < 2; ch++) {
        #pragma unroll
        for (int v = tid; v < BM * 16; v += 256) {
            int row = v >> 4, seg = v & 15;
            uint32_t so = row * ASTR + (ch * 16 + seg) * 16;
            size_t ga = (size_t)(m0 + row) * KK + ch * 128 + seg * 8;
            cp16(sAH + so, Xh + ga);
            cp16(sAL + so, Xl + ga);
        }
        cp_commit();
    }

    float acc[4][4];
    #pragma unroll
    for (int nt = 0; nt < 4; nt++)
        #pragma unroll
        for (int q = 0; q < 4; q++) acc[nt][q] = 0.f;

    uint32_t aoff = (wm + (lane & 15)) * ASTR + (lane >> 4) * 16;
    uint32_t boff0 = (wn + (lane & 7) + ((lane >> 4) << 3)) * ASTR + (((lane >> 3) & 1) * 16);
    uint32_t boff1 = boff0 + 16 * ASTR;

    auto compute_range = [&](int k0, int k1) {
        #pragma unroll
        for (int ks = k0; ks < k1; ks++) {
            uint32_t ko = ks * 32;
            uint32_t ah[4], al[4], bh[2][4], bl[2][4];
            ldmx4(ah, sAH + aoff + ko);
            ldmx4(al, sAL + aoff + ko);
            ldmx4(bh[0], sBH + boff0 + ko);
            ldmx4(bl[0], sBL + boff0 + ko);
            ldmx4(bh[1], sBH + boff1 + ko);
            ldmx4(bl[1], sBL + boff1 + ko);
            #pragma unroll
            for (int nt = 0; nt < 4; nt++) {
                const uint32_t* b2h = &bh[nt >> 1][(nt & 1) * 2];
                const uint32_t* b2l = &bl[nt >> 1][(nt & 1) * 2];
                mma16816(acc[nt], ah, b2h);
                mma16816(acc[nt], ah, b2l);
                mma16816(acc[nt], al, b2h);
            }
        }
    };
    cp_wait<1>(); __syncthreads();
    compute_range(0, 8);
    cp_wait<0>(); __syncthreads();
    compute_range(8, 16);

    int rb = m0 + wm + (lane >> 2);
    int cb = n0 + wn + (lane & 3) * 2;
    #pragma unroll
    for (int nt = 0; nt < 4; nt++) {
        int cc = cb + nt * 8;
        *reinterpret_cast<float2*>(&S[(size_t)rb * HID + cc]) = make_float2(acc[nt][0], acc[nt][1]);
        *reinterpret_cast<float2*>(&S[(size_t)(rb + 8) * HID + cc]) = make_float2(acc[nt][2], acc[nt][3]);
    }
    gdc_launch();
}
#define SMEM_K256 (4 * BM * (256 * 2 + 16))

// ---------------- persistent mid-loop: 12 x (agg -> gemm), 1 kernel, 11 grid barriers ----
#define GF_ASTR 400
#define GF_ASLAB (64 * GF_ASTR)
#define GF_BSLAB (192 * GF_ASTR)
#define GF_SMEM (2 * GF_ASLAB + 2 * GF_BSLAB)   // 204800 -> 1 CTA/SM, grid 128 co-resident

__global__ void __launch_bounds__(512, 1)
persist(const __nv_bfloat16* __restrict__ Wh, const __nv_bfloat16* __restrict__ Wl,
        const float* __restrict__ b1, const float* __restrict__ b_mid,
        const float* __restrict__ features,
        float* __restrict__ sa, float* __restrict__ sbuf, float* __restrict__ fb,
        const int* __restrict__ nidx, const float* __restrict__ nval,
        const int* __restrict__ ncnt)
{
    extern __shared__ char smem[];
    uint32_t sb = smem_u32(smem);
    const uint32_t sAH = sb, sAL = sb + GF_ASLAB;
    const uint32_t sBH = sb + 2 * GF_ASLAB, sBL = sb + 2 * GF_ASLAB + GF_BSLAB;
    int tid = threadIdx.x, w = tid >> 5, lane = tid & 31;
    int m0 = blockIdx.x * 64;
    int wm = (w & 3) * 16, wn = (w >> 2) * 48;
    uint32_t aoff = (wm + (lane & 15)) * GF_ASTR + (lane >> 4) * 16;
    uint32_t bbase = (wn + (lane & 7) + ((lane >> 4) << 3)) * GF_ASTR + (((lane >> 3) & 1) * 16);
    int halfl = lane >> 4, sl = lane & 15;

    for (int it = 0; it < 12; it++) {
        // --- prefetch this layer's weight tile (overlaps barrier spin) ---
        const __nv_bfloat16* WH = Wh + (size_t)192 * 256 + (size_t)it * 192 * 192;
        const __nv_bfloat16* WL = Wl + (size_t)192 * 256 + (size_t)it * 192 * 192;
        for (int v = tid; v < 192 * 24; v += 512) {
            int row = v / 24, seg = v % 24;
            uint32_t so = row * GF_ASTR + seg * 16;
            size_t g = (size_t)row * 192 + seg * 8;
            cp16(sBH + so, WH + g);
            cp16(sBL + so, WL + g);
        }
        cp_commit();

        if (it == 0) gdc_wait();     // sa ready from gemm_os
        else grid_barrier(tid);      // S(it-1) visible chip-wide

        const float* Sin = (it & 1) ? sbuf : sa;
        float* Sout = (it & 1) ? sa : sbuf;
        int mode = (it == 0) ? 0 : (it == 1) ? 1 : ((it & 1) ? 2 : 0);
        const float* bias = (it == 0) ? b1 : b_mid + (size_t)(it - 1) * HID;

        // --- agg: 4 rows per warp; output written straight into smem A slabs ---
        for (int rr = 0; rr < 4; rr++) {
            int lr = (w << 2) + rr;
            int row = m0 + lr;
            int cnt = ncnt[row];
            const int* ni = nidx + (size_t)row * MAXN;
            const float* nv = nval + (size_t)row * MAXN;
            float a0 = 0.f, a1 = 0.f, a2 = 0.f, a3 = 0.f;
            float c0a = 0.f, c1a = 0.f, c2a = 0.f, c3a = 0.f;
            for (int i = 0; i < cnt; i += 8) {
                int4   jA = *reinterpret_cast<const int4*>(ni + i);
                int4   jB = *reinterpret_cast<const int4*>(ni + i + 4);
                float4 uA = *reinterpret_cast<const float4*>(nv + i);
                float4 uB = *reinterpret_cast<const float4*>(nv + i + 4);
                int   n0 = halfl ? jA.y : jA.x;  float w0 = halfl ? uA.y : uA.x;
                int   n1 = halfl ? jA.w : jA.z;  float w1 = halfl ? uA.w : uA.z;
                int   n2 = halfl ? jB.y : jB.x;  float w2 = halfl ? uB.y : uB.x;
                int   n3 = halfl ? jB.w : jB.z;  float w3 = halfl ? uB.w : uB.z;
                float4 v0 = __ldcg(reinterpret_cast<const float4*>(Sin + (size_t)n0 * HID + 4 * sl));
                float4 v1 = __ldcg(reinterpret_cast<const float4*>(Sin + (size_t)n1 * HID + 4 * sl));
                float4 v2 = __ldcg(reinterpret_cast<const float4*>(Sin + (size_t)n2 * HID + 4 * sl));
                float4 v3 = __ldcg(reinterpret_cast<const float4*>(Sin + (size_t)n3 * HID + 4 * sl));
                a0  = fmaf(w0, v0.x, a0);  a1  = fmaf(w0, v0.y, a1);
                a2  = fmaf(w0, v0.z, a2);  a3  = fmaf(w0, v0.w, a3);
                c0a = fmaf(w1, v1.x, c0a); c1a = fmaf(w1, v1.y, c1a);
                c2a = fmaf(w1, v1.z, c2a); c3a = fmaf(w1, v1.w, c3a);
                a0  = fmaf(w2, v2.x, a0);  a1  = fmaf(w2, v2.y, a1);
                a2  = fmaf(w2, v2.z, a2);  a3  = fmaf(w2, v2.w, a3);
                c0a = fmaf(w3, v3.x, c0a); c1a = fmaf(w3, v3.y, c1a);
                c2a = fmaf(w3, v3.z, c2a); c3a = fmaf(w3, v3.w, c3a);
            }
            a0 += c0a; a1 += c1a; a2 += c2a; a3 += c3a;
            a0 += __shfl_xor_sync(0xffffffffu, a0, 16);
            a1 += __shfl_xor_sync(0xffffffffu, a1, 16);
            a2 += __shfl_xor_sync(0xffffffffu, a2, 16);
            a3 += __shfl_xor_sync(0xffffffffu, a3, 16);

            size_t rbase = (size_t)row * HID;
            char* rowH = smem + (size_t)lr * GF_ASTR;
            char* rowL = smem + GF_ASLAB + (size_t)lr * GF_ASTR;

            if (lane < 16) {
                int c = 4 * sl;
                float4 bs = *reinterpret_cast<const float4*>(bias + c);
                float t0 = fmaxf(a0 + bs.x, 0.f), t1 = fmaxf(a1 + bs.y, 0.f);
                float t2 = fmaxf(a2 + bs.z, 0.f), t3 = fmaxf(a3 + bs.w, 0.f);
                if (mode == 1) {
                    float4 rv = *reinterpret_cast<const float4*>(features + (size_t)row * INF + c);
                    t0 = (rv.x + t0) * 0.5f; t1 = (rv.y + t1) * 0.5f;
                    t2 = (rv.z + t2) * 0.5f; t3 = (rv.w + t3) * 0.5f;
                }
                if (mode == 2) {
                    float4 rv = *reinterpret_cast<const float4*>(fb + rbase + c);
                    t0 = (rv.x + t0) * 0.5f; t1 = (rv.y + t1) * 0.5f;
                    t2 = (rv.z + t2) * 0.5f; t3 = (rv.w + t3) * 0.5f;
                }
                if (mode >= 1)
                    *reinterpret_cast<float4*>(fb + rbase + c) = make_float4(t0, t1, t2, t3);
                split_store4_smem(t0, t1, t2, t3, rowH + c * 2, rowL + c * 2);
            }
            {
                int c = 64 + 4 * lane;
                float4 sv = __ldcg(reinterpret_cast<const float4*>(Sin + rbase + c));
                float4 bs = *reinterpret_cast<const float4*>(bias + c);
                float t0 = fmaxf(sv.x + bs.x, 0.f), t1 = fmaxf(sv.y + bs.y, 0.f);
                float t2 = fmaxf(sv.z + bs.z, 0.f), t3 = fmaxf(sv.w + bs.w, 0.f);
                if (mode == 1) {
                    float4 rv = *reinterpret_cast<const float4*>(features + (size_t)row * INF + c);
                    t0 = (rv.x + t0) * 0.5f; t1 = (rv.y + t1) * 0.5f;
                    t2 = (rv.z + t2) * 0.5f; t3 = (rv.w + t3) * 0.5f;
                }
                if (mode == 2) {
                    float4 rv = *reinterpret_cast<const float4*>(fb + rbase + c);
                    t0 = (rv.x + t0) * 0.5f; t1 = (rv.y + t1) * 0.5f;
                    t2 = (rv.z + t2) * 0.5f; t3 = (rv.w + t3) * 0.5f;
                }
                if (mode >= 1)
                    *reinterpret_cast<float4*>(fb + rbase + c) = make_float4(t0, t1, t2, t3);
                split_store4_smem(t0, t1, t2, t3, rowH + c * 2, rowL + c * 2);
            }
        }

        cp_wait<0>();        // weight tile landed
        __syncthreads();     // A slabs + W visible to all warps

        // --- gemm: 12 k-steps, A already in smem ---
        float acc[6][4];
        #pragma unroll
        for (int nt = 0; nt < 6; nt++)
            #pragma unroll
            for (int q = 0; q < 4; q++) acc[nt][q] = 0.f;

        #pragma unroll
        for (int ks = 0; ks < 12; ks++) {
            uint32_t ko = ks * 32;
            uint32_t ah[4], al[4], bh[3][4], bl[3][4];
            ldmx4(ah, sAH + aoff + ko);
            ldmx4(al, sAL + aoff + ko);
            #pragma unroll
            for (int p = 0; p < 3; p++) {
                uint32_t bo = bbase + p * 16 * GF_ASTR + ko;
                ldmx4(bh[p], sBH + bo);
                ldmx4(bl[p], sBL + bo);
            }
            #pragma unroll
            for (int nt = 0; nt < 6; nt++) {
                const uint32_t* b2h = &bh[nt >> 1][(nt & 1) * 2];
                const uint32_t* b2l = &bl[nt >> 1][(nt & 1) * 2];
                mma16816(acc[nt], ah, b2h);
                mma16816(acc[nt], ah, b2l);
                mma16816(acc[nt], al, b2h);
            }
        }

        int rb = m0 + wm + (lane >> 2);
        int cb = wn + (lane & 3) * 2;
        #pragma unroll
        for (int nt = 0; nt < 6; nt++) {
            int cc = cb + nt * 8;
            *reinterpret_cast<float2*>(&Sout[(size_t)rb * HID + cc]) =
                make_float2(acc[nt][0], acc[nt][1]);
            *reinterpret_cast<float2*>(&Sout[(size_t)(rb + 8) * HID + cc]) =
                make_float2(acc[nt][2], acc[nt][3]);
        }
        __syncthreads();     // all B reads done before next layer's W prefetch
    }
    gdc_launch();
}

// ---------------- fused tail (gc13 + feat @ W_out) ----------------
__global__ __launch_bounds__(256) void tail_fused(const float* __restrict__ S,
                                                  const float* __restrict__ bias,
                                                  float* __restrict__ fb,
                                                  float* __restrict__ feat_out,
                                                  const float* __restrict__ W_out,
                                                  float* __restrict__ sup3,
                                                  const int* __restrict__ nidx,
                                                  const float* __restrict__ nval,
                                                  const int* __restrict__ ncnt)
{
    gdc_wait();
    int row = (blockIdx.x * blockDim.x + threadIdx.x) >> 5;
    int lane = threadIdx.x & 31;
    int cnt = ncnt[row];
    const int* ni = nidx + (size_t)row * MAXN;
    const float* nv = nval + (size_t)row * MAXN;
    float acc0 = 0.f, acc1 = 0.f, e0 = 0.f, e1 = 0.f;
    for (int i = 0; i < cnt; i += 4) {
        int4   ji = *reinterpret_cast<const int4*>(ni + i);
        float4 ui = *reinterpret_cast<const float4*>(nv + i);
        const float* s0 = S + (size_t)ji.x * HID;
        const float* s1 = S + (size_t)ji.y * HID;
        const float* s2 = S + (size_t)ji.z * HID;
        const float* s3 = S + (size_t)ji.w * HID;
        acc0 = fmaf(ui.x, s0[lane], acc0);  acc1 = fmaf(ui.x, s0[lane + 32], acc1);
        e0   = fmaf(ui.y, s1[lane], e0);    e1   = fmaf(ui.y, s1[lane + 32], e1);
        acc0 = fmaf(ui.z, s2[lane], acc0);  acc1 = fmaf(ui.z, s2[lane + 32], acc1);
        e0   = fmaf(ui.w, s3[lane], e0);    e1   = fmaf(ui.w, s3[lane + 32], e1);
    }
    acc0 += e0; acc1 += e1;

    float w0s = 0.f, w1s = 0.f, w2s = 0.f;
    size_t rbase = (size_t)row * HID;
    #pragma unroll
    for (int j = 0; j < 6; j++) {
        int c = 32 * j + lane;
        float t = (j == 0) ? acc0 : (j == 1) ? acc1 : S[rbase + c];
        t += bias[c];
        t = fmaxf(t, 0.f);
        t = (fb[rbase + c] + t) * 0.5f;
        fb[rbase + c] = t;
        feat_out[rbase + c] = t;
        w0s = fmaf(t, W_out[c * 3 + 0], w0s);
        w1s = fmaf(t, W_out[c * 3 + 1], w1s);
        w2s = fmaf(t, W_out[c * 3 + 2], w2s);
    }
    #pragma unroll
    for (int d = 16; d; d >>= 1) {
        w0s += __shfl_xor_sync(0xffffffffu, w0s, d);
        w1s += __shfl_xor_sync(0xffffffffu, w1s, d);
        w2s += __shfl_xor_sync(0xffffffffu, w2s, d);
    }
    if (lane == 0) {
        sup3[row * 3 + 0] = w0s;
        sup3[row * 3 + 1] = w1s;
        sup3[row * 3 + 2] = w2s;
    }
    gdc_launch();
}

// ---------------- coords ----------------
__global__ __launch_bounds__(256) void agg_coords(const float* __restrict__ S,
                                                  const float* __restrict__ bias,
                                                  float* __restrict__ out,
                                                  const int* __restrict__ nidx,
                                                  const float* __restrict__ nval,
                                                  const int* __restrict__ ncnt)
{
    gdc_wait();
    int warp = (blockIdx.x * blockDim.x + threadIdx.x) >> 5;
    int lane = threadIdx.x & 31;
    int cnt = ncnt[warp];
    const int* ni = nidx + (size_t)warp * MAXN;
    const float* nv = nval + (size_t)warp * MAXN;
    float acc0 = 0.f;
    for (int i = 0; i < cnt; i++) {
        if (lane < 2) acc0 = fmaf(nv[i], S[(size_t)ni[i] * 3 + lane], acc0);
    }
    if (lane < 3) {
        float t = (lane < 2) ? acc0 : S[(size_t)warp * 3 + lane];
        out[(size_t)warp * 3 + lane] = t + bias[lane];
    }
}

// ---------------- host PDL launcher ----------------
template <typename F, typename... Args>
static inline void pdl(F fn, dim3 g, dim3 b, size_t sm, Args... args)
{
    cudaLaunchConfig_t cfg = {};
    cfg.gridDim = g; cfg.blockDim = b; cfg.dynamicSmemBytes = sm; cfg.stream = 0;
    cudaLaunchAttribute at;
    at.id = cudaLaunchAttributeProgrammaticStreamSerialization;
    at.val.programmaticStreamSerializationAllowed = 1;
    cfg.attrs = &at; cfg.numAttrs = 1;
    cudaLaunchKernelEx(&cfg, fn, args...);
}

extern "C" void kernel_launch(void* const* d_in, const int* in_sizes, int n_in,
                              void* d_out, int out_size)
{
    const float* features = (const float*)d_in[0];
    const float* adj      = (const float*)d_in[1];
    const float* W1       = (const float*)d_in[2];
    const float* b1       = (const float*)d_in[3];
    const float* W_mid    = (const float*)d_in[4];
    const float* b_mid    = (const float*)d_in[5];
    const float* W_out    = (const float*)d_in[6];
    const float* b_out    = (const float*)d_in[7];
    float* out = (float*)d_out;
    float* coords   = out;
    float* feat_out = out + NN * 3;

    float *sa, *sbuf, *fb, *sup3, *nval;
    __nv_bfloat16 *xhi, *xlo, *whi, *wlo;
    int *nidx, *ncnt;
    cudaGetSymbolAddress((void**)&sa,   g_supA);
    cudaGetSymbolAddress((void**)&sbuf, g_supB);
    cudaGetSymbolAddress((void**)&fb,   g_featbuf);
    cudaGetSymbolAddress((void**)&sup3, g_sup3);
    cudaGetSymbolAddress((void**)&xhi,  g_xhi);
    cudaGetSymbolAddress((void**)&xlo,  g_xlo);
    cudaGetSymbolAddress((void**)&whi,  g_wthi);
    cudaGetSymbolAddress((void**)&wlo,  g_wtlo);
    cudaGetSymbolAddress((void**)&nidx, g_nidx);
    cudaGetSymbolAddress((void**)&nval, g_nval);
    cudaGetSymbolAddress((void**)&ncnt, g_ncnt);

    cudaFuncSetAttribute(gemm_os, cudaFuncAttributeMaxDynamicSharedMemorySize, SMEM_K256);
    cudaFuncSetAttribute(persist, cudaFuncAttributeMaxDynamicSharedMemorySize, GF_SMEM);

    build_csr<<<NN / 8, 256>>>(adj, nidx, nval, ncnt);
    pdl(convert_weights, dim3((WT_TOTAL + 255) / 256), dim3(256), (size_t)0, W1, W_mid, whi, wlo);
    pdl(convert_features, dim3((NN * INF + 255) / 256), dim3(256), (size_t)0, features, xhi, xlo);

    pdl(gemm_os, dim3(NN / BM, HID / BN), dim3(256), (size_t)SMEM_K256,
        (const __nv_bfloat16*)xhi, (const __nv_bfloat16*)xlo,
        (const __nv_bfloat16*)whi, (const __nv_bfloat16*)wlo, sa);

    pdl(persist, dim3(NN / 64), dim3(512), (size_t)GF_SMEM,
        (const __nv_bfloat16*)whi, (const __nv_bfloat16*)wlo,
        (const float*)b1, (const float*)b_mid, features,
        sa, sbuf, fb,
        (const int*)nidx, (const float*)nval, (const int*)ncnt);

    pdl(tail_fused, dim3(NN / 8), dim3(256), (size_t)0,
        (const float*)sa, (const float*)(b_mid + (size_t)11 * HID), fb, feat_out,
        W_out, sup3, (const int*)nidx, (const float*)nval, (const int*)ncnt);
    pdl(agg_coords, dim3(NN / 8), dim3(256), (size_t)0,
        (const float*)sup3, b_out, coords,
        (const int*)nidx, (const float*)nval, (const int*)ncnt);
}

// round 16
// speedup vs baseline: 1.1335x; 1.1166x over previous
#include <cuda_runtime.h>
#include <cuda_bf16.h>
#include <cstdint>
#include <cstddef>

#define NN   8192
#define HID  192
#define INF  256
#define MAXN 128

__device__ float g_supA[NN * HID];
__device__ float g_supB[NN * HID];
__device__ float g_featbuf[NN * HID];
__device__ float g_sup3[NN * 3];
__device__ __nv_bfloat16 g_xhi[NN * INF];
__device__ __nv_bfloat16 g_xlo[NN * INF];
#define WT_TOTAL (192*256 + 12*192*192)
__device__ __nv_bfloat16 g_wthi[WT_TOTAL];
__device__ __nv_bfloat16 g_wtlo[WT_TOTAL];
__device__ int   g_nidx[NN * MAXN];
__device__ float g_nval[NN * MAXN];
__device__ int   g_ncnt[NN];

__device__ __forceinline__ uint32_t smem_u32(const void* p) {
    uint32_t a;
    asm("{ .reg .u64 t; cvta.to.shared.u64 t, %1; cvt.u32.u64 %0, t; }" : "=r"(a) : "l"(p));
    return a;
}
__device__ __forceinline__ void cp16(uint32_t d, const void* s) {
    asm volatile("cp.async.cg.shared.global [%0], [%1], 16;" :: "r"(d), "l"(s));
}
__device__ __forceinline__ void cp_commit() { asm volatile("cp.async.commit_group;" ::: "memory"); }
template <int N> __device__ __forceinline__ void cp_wait() {
    asm volatile("cp.async.wait_group %0;" :: "n"(N) : "memory");
}
__device__ __forceinline__ void ldmx4(uint32_t* r, uint32_t a) {
    asm volatile("ldmatrix.sync.aligned.m8n8.x4.shared.b16 {%0,%1,%2,%3}, [%4];"
        : "=r"(r[0]), "=r"(r[1]), "=r"(r[2]), "=r"(r[3]) : "r"(a));
}
__device__ __forceinline__ void mma16816(float* d, const uint32_t* a, const uint32_t* b) {
    asm volatile("mma.sync.aligned.m16n8k16.row.col.f32.bf16.bf16.f32 "
        "{%0,%1,%2,%3}, {%4,%5,%6,%7}, {%8,%9}, {%0,%1,%2,%3};"
        : "+f"(d[0]), "+f"(d[1]), "+f"(d[2]), "+f"(d[3])
        : "r"(a[0]), "r"(a[1]), "r"(a[2]), "r"(a[3]), "r"(b[0]), "r"(b[1]));
}
__device__ __forceinline__ void gdc_launch() { asm volatile("griddepcontrol.launch_dependents;"); }
__device__ __forceinline__ void gdc_wait()   { asm volatile("griddepcontrol.wait;" ::: "memory"); }

__device__ __forceinline__ void split_store4(float t0, float t1, float t2, float t3,
                                             __nv_bfloat16* ohi, __nv_bfloat16* olo, size_t idx)
{
    __nv_bfloat16 h0 = __float2bfloat16(t0), h1 = __float2bfloat16(t1);
    __nv_bfloat16 h2 = __float2bfloat16(t2), h3 = __float2bfloat16(t3);
    __nv_bfloat162 a; a.x = h0; a.y = h1;
    __nv_bfloat162 b; b.x = h2; b.y = h3;
    *reinterpret_cast<__nv_bfloat162*>(ohi + idx)     = a;
    *reinterpret_cast<__nv_bfloat162*>(ohi + idx + 2) = b;
    __nv_bfloat162 c, d;
    c.x = __float2bfloat16(t0 - __bfloat162float(h0));
    c.y = __float2bfloat16(t1 - __bfloat162float(h1));
    d.x = __float2bfloat16(t2 - __bfloat162float(h2));
    d.y = __float2bfloat16(t3 - __bfloat162float(h3));
    *reinterpret_cast<__nv_bfloat162*>(olo + idx)     = c;
    *reinterpret_cast<__nv_bfloat162*>(olo + idx + 2) = d;
}

// ---------------- CSR extraction (pads each row to multiple of 8) ----------------
__global__ __launch_bounds__(256) void build_csr(const float* __restrict__ adj,
                                                 int* __restrict__ nidx,
                                                 float* __restrict__ nval,
                                                 int* __restrict__ ncnt)
{
    int warp = (blockIdx.x * blockDim.x + threadIdx.x) >> 5;
    int lane = threadIdx.x & 31;
    const float4* row = reinterpret_cast<const float4*>(adj + (size_t)warp * NN);
    int* my_idx = nidx + (size_t)warp * MAXN;
    float* my_val = nval + (size_t)warp * MAXN;
    int count = 0;
    for (int it = 0; it < NN / 128; it++) {
        float4 v = row[it * 32 + lane];
        int c0 = it * 128 + lane * 4;
        int my = (v.x != 0.f) + (v.y != 0.f) + (v.z != 0.f) + (v.w != 0.f);
        int inc = my;
        #pragma unroll
        for (int d = 1; d < 32; d <<= 1) {
            int t = __shfl_up_sync(0xffffffffu, inc, d);
            if (lane >= d) inc += t;
        }
        int total = __shfl_sync(0xffffffffu, inc, 31);
        int pos = count + inc - my;
        if (v.x != 0.f) { if (pos < MAXN) { my_idx[pos] = c0;     my_val[pos] = v.x; } pos++; }
        if (v.y != 0.f) { if (pos < MAXN) { my_idx[pos] = c0 + 1; my_val[pos] = v.y; } pos++; }
        if (v.z != 0.f) { if (pos < MAXN) { my_idx[pos] = c0 + 2; my_val[pos] = v.z; } pos++; }
        if (v.w != 0.f) { if (pos < MAXN) { my_idx[pos] = c0 + 3; my_val[pos] = v.w; } pos++; }
        count += total;
    }
    if (count > MAXN) count = MAXN;
    int padded = (count + 7) & ~7;
    if (padded > MAXN) padded = MAXN;
    for (int s = count + lane; s < padded; s += 32) { my_idx[s] = 0; my_val[s] = 0.f; }
    if (lane == 0) ncnt[warp] = padded;
    gdc_launch();
}

__global__ __launch_bounds__(256) void convert_weights(const float* __restrict__ W1,
                                                       const float* __restrict__ W_mid,
                                                       __nv_bfloat16* __restrict__ whi,
                                                       __nv_bfloat16* __restrict__ wlo)
{
    int idx = blockIdx.x * blockDim.x + threadIdx.x;
    if (idx < WT_TOTAL) {
        float w;
        if (idx < 192 * 256) {
            int n = idx / 256, k = idx % 256;
            w = W1[k * 192 + n];
        } else {
            int rel = idx - 192 * 256;
            int i = rel / (192 * 192), r = rel % (192 * 192);
            int n = r / 192, k = r % 192;
            w = W_mid[(size_t)i * 192 * 192 + k * 192 + n];
        }
        __nv_bfloat16 h = __float2bfloat16(w);
        whi[idx] = h;
        wlo[idx] = __float2bfloat16(w - __bfloat162float(h));
    }
    gdc_launch();
}

__global__ __launch_bounds__(256) void convert_features(const float* __restrict__ f,
                                                        __nv_bfloat16* __restrict__ xhi,
                                                        __nv_bfloat16* __restrict__ xlo)
{
    int idx = blockIdx.x * blockDim.x + threadIdx.x;
    if (idx < NN * INF) {
        float v = f[idx];
        __nv_bfloat16 h = __float2bfloat16(v);
        xhi[idx] = h;
        xlo[idx] = __float2bfloat16(v - __bfloat162float(h));
    }
    gdc_launch();
}

// ---------------- gc1 GEMM: BM=64, BN=192, K=256 in two K=128 phases, 512 thr ----------------
// Single wave (grid 128); A read once. Same warp layout as gemm_full.
#define OS_ASTR 272                       // 128 bf16 cols * 2B + 16 pad
#define OS_ASLAB (64 * OS_ASTR)           // 17408
#define OS_BSLAB (192 * OS_ASTR)          // 52224
#define OS_SMEM (2 * OS_ASLAB + 2 * OS_BSLAB)   // 139264

__global__ void __launch_bounds__(512, 1)
gemm_os(const __nv_bfloat16* __restrict__ Xh, const __nv_bfloat16* __restrict__ Xl,
        const __nv_bfloat16* __restrict__ Wh, const __nv_bfloat16* __restrict__ Wl,
        float* __restrict__ S)
{
    constexpr int KK = 256;
    extern __shared__ char smem[];
    uint32_t sb = smem_u32(smem);
    const uint32_t sAH = sb, sAL = sb + OS_ASLAB;
    const uint32_t sBH = sb + 2 * OS_ASLAB, sBL = sb + 2 * OS_ASLAB + OS_BSLAB;
    int tid = threadIdx.x;
    int m0 = blockIdx.x * 64;
    int w = tid >> 5, lane = tid & 31;
    int wm = (w & 3) * 16, wn = (w >> 2) * 48;

    auto load_B = [&](int ph) {   // 192 rows x 16 segs (128 cols)
        #pragma unroll
        for (int v = tid; v < 192 * 16; v += 512) {
            int row = v >> 4, seg = v & 15;
            uint32_t so = row * OS_ASTR + seg * 16;
            size_t g = (size_t)row * KK + ph * 128 + seg * 8;
            cp16(sBH + so, Wh + g);
            cp16(sBL + so, Wl + g);
        }
    };
    auto load_A = [&](int ph) {   // 64 rows x 16 segs
        #pragma unroll
        for (int v = tid; v < 64 * 16; v += 512) {
            int row = v >> 4, seg = v & 15;
            uint32_t so = row * OS_ASTR + seg * 16;
            size_t g = (size_t)(m0 + row) * KK + ph * 128 + seg * 8;
            cp16(sAH + so, Xh + g);
            cp16(sAL + so, Xl + g);
        }
    };

    float acc[6][4];
    #pragma unroll
    for (int nt = 0; nt < 6; nt++)
        #pragma unroll
        for (int q = 0; q < 4; q++) acc[nt][q] = 0.f;

    uint32_t aoff = (wm + (lane & 15)) * OS_ASTR + (lane >> 4) * 16;
    uint32_t bbase = (wn + (lane & 7) + ((lane >> 4) << 3)) * OS_ASTR + (((lane >> 3) & 1) * 16);

    auto compute_phase = [&]() {
        #pragma unroll
        for (int ks = 0; ks < 8; ks++) {
            uint32_t ko = ks * 32;
            uint32_t ah[4], al[4], bh[3][4], bl[3][4];
            ldmx4(ah, sAH + aoff + ko);
            ldmx4(al, sAL + aoff + ko);
            #pragma unroll
            for (int p = 0; p < 3; p++) {
                uint32_t bo = bbase + p * 16 * OS_ASTR + ko;
                ldmx4(bh[p], sBH + bo);
                ldmx4(bl[p], sBL + bo);
            }
            #pragma unroll
            for (int nt = 0; nt < 6; nt++) {
                const uint32_t* b2h = &bh[nt >> 1][(nt & 1) * 2];
                const uint32_t* b2l = &bl[nt >> 1][(nt & 1) * 2];
                mma16816(acc[nt], ah, b2h);
                mma16816(acc[nt], ah, b2l);
                mma16816(acc[nt], al, b2h);
            }
        }
    };

    // phase 0: B pre-wait (weights independent of predecessor), A post-wait
    load_B(0); cp_commit();
    gdc_wait();
    load_A(0); cp_commit();
    cp_wait<0>(); __syncthreads();
    compute_phase();
    __syncthreads();                 // all smem reads done before overwrite
    // phase 1: reuse buffers
    load_B(1); load_A(1); cp_commit();
    cp_wait<0>(); __syncthreads();
    compute_phase();

    int rb = m0 + wm + (lane >> 2);
    int cb = wn + (lane & 3) * 2;
    #pragma unroll
    for (int nt = 0; nt < 6; nt++) {
        int cc = cb + nt * 8;
        *reinterpret_cast<float2*>(&S[(size_t)rb * HID + cc]) = make_float2(acc[nt][0], acc[nt][1]);
        *reinterpret_cast<float2*>(&S[(size_t)(rb + 8) * HID + cc]) = make_float2(acc[nt][2], acc[nt][3]);
    }
    gdc_launch();
}

// ---------------- mid GEMM: BM=64, BN=192, K=192, 512 thr; launch at END ----------------
#define GF_ASTR 400
#define GF_ASLAB (64 * GF_ASTR)
#define GF_BSLAB (192 * GF_ASTR)
#define GF_SMEM (2 * GF_ASLAB + 2 * GF_BSLAB)

__global__ void __launch_bounds__(512, 1)
gemm_full(const __nv_bfloat16* __restrict__ Xh, const __nv_bfloat16* __restrict__ Xl,
          const __nv_bfloat16* __restrict__ Wh, const __nv_bfloat16* __restrict__ Wl,
          float* __restrict__ S)
{
    extern __shared__ char smem[];
    uint32_t sb = smem_u32(smem);
    const uint32_t sAH = sb, sAL = sb + GF_ASLAB;
    const uint32_t sBH = sb + 2 * GF_ASLAB, sBL = sb + 2 * GF_ASLAB + GF_BSLAB;
    int tid = threadIdx.x;
    int m0 = blockIdx.x * 64;
    int w = tid >> 5, lane = tid & 31;
    int wm = (w & 3) * 16, wn = (w >> 2) * 48;

    #pragma unroll
    for (int v = tid; v < 192 * 24; v += 512) {
        int row = v / 24, seg = v % 24;
        uint32_t so = row * GF_ASTR + seg * 16;
        size_t g = (size_t)row * 192 + seg * 8;
        cp16(sBH + so, Wh + g);
        cp16(sBL + so, Wl + g);
    }
    cp_commit();
    gdc_wait();
    #pragma unroll
    for (int ch = 0; ch < 2; ch++) {
        #pragma unroll
        for (int v = tid; v < 64 * 12; v += 512) {
            int row = v / 12, seg = v % 12;
            uint32_t so = row * GF_ASTR + (ch * 12 + seg) * 16;
            size_t g = (size_t)(m0 + row) * 192 + ch * 96 + seg * 8;
            cp16(sAH + so, Xh + g);
            cp16(sAL + so, Xl + g);
        }
        cp_commit();
    }

    float acc[6][4];
    #pragma unroll
    for (int nt = 0; nt < 6; nt++)
        #pragma unroll
        for (int q = 0; q < 4; q++) acc[nt][q] = 0.f;

    uint32_t aoff = (wm + (lane & 15)) * GF_ASTR + (lane >> 4) * 16;
    uint32_t bbase = (wn + (lane & 7) + ((lane >> 4) << 3)) * GF_ASTR + (((lane >> 3) & 1) * 16);

    auto compute_range = [&](int k0, int k1) {
        #pragma unroll
        for (int ks = k0; ks < k1; ks++) {
            uint32_t ko = ks * 32;
            uint32_t ah[4], al[4], bh[3][4], bl[3][4];
            ldmx4(ah, sAH + aoff + ko);
            ldmx4(al, sAL + aoff + ko);
            #pragma unroll
            for (int p = 0; p < 3; p++) {
                uint32_t bo = bbase + p * 16 * GF_ASTR + ko;
                ldmx4(bh[p], sBH + bo);
                ldmx4(bl[p], sBL + bo);
            }
            #pragma unroll
            for (int nt = 0; nt < 6; nt++) {
                const uint32_t* b2h = &bh[nt >> 1][(nt & 1) * 2];
                const uint32_t* b2l = &bl[nt >> 1][(nt & 1) * 2];
                mma16816(acc[nt], ah, b2h);
                mma16816(acc[nt], ah, b2l);
                mma16816(acc[nt], al, b2h);
            }
        }
    };
    cp_wait<1>(); __syncthreads();
    compute_range(0, 6);
    cp_wait<0>(); __syncthreads();
    compute_range(6, 12);

    int rb = m0 + wm + (lane >> 2);
    int cb = wn + (lane & 3) * 2;
    #pragma unroll
    for (int nt = 0; nt < 6; nt++) {
        int cc = cb + nt * 8;
        *reinterpret_cast<float2*>(&S[(size_t)rb * HID + cc]) = make_float2(acc[nt][0], acc[nt][1]);
        *reinterpret_cast<float2*>(&S[(size_t)(rb + 8) * HID + cc]) = make_float2(acc[nt][2], acc[nt][3]);
    }
    gdc_launch();
}

// ---------------- aggregation: float4 gathers, 8-wide unroll; wait entry, launch END ----------------
template <int MODE>
__global__ __launch_bounds__(256) void agg2(const float* __restrict__ S,
                                            const float* __restrict__ bias,
                                            const float* __restrict__ resptr,
                                            float* __restrict__ fbout,
                                            __nv_bfloat16* __restrict__ ohi,
                                            __nv_bfloat16* __restrict__ olo,
                                            const int* __restrict__ nidx,
                                            const float* __restrict__ nval,
                                            const int* __restrict__ ncnt)
{
    gdc_wait();
    int row = (blockIdx.x * blockDim.x + threadIdx.x) >> 5;
    int lane = threadIdx.x & 31;
    int half = lane >> 4, sl = lane & 15;
    int cnt = ncnt[row];
    const int* ni = nidx + (size_t)row * MAXN;
    const float* nv = nval + (size_t)row * MAXN;

    float a0 = 0.f, a1 = 0.f, a2 = 0.f, a3 = 0.f;
    float b0 = 0.f, b1 = 0.f, b2 = 0.f, b3 = 0.f;
    for (int i = 0; i < cnt; i += 8) {
        int4   jA = *reinterpret_cast<const int4*>(ni + i);
        int4   jB = *reinterpret_cast<const int4*>(ni + i + 4);
        float4 uA = *reinterpret_cast<const float4*>(nv + i);
        float4 uB = *reinterpret_cast<const float4*>(nv + i + 4);
        int   n0 = half ? jA.y : jA.x;  float w0 = half ? uA.y : uA.x;
        int   n1 = half ? jA.w : jA.z;  float w1 = half ? uA.w : uA.z;
        int   n2 = half ? jB.y : jB.x;  float w2 = half ? uB.y : uB.x;
        int   n3 = half ? jB.w : jB.z;  float w3 = half ? uB.w : uB.z;
        float4 v0 = *reinterpret_cast<const float4*>(S + (size_t)n0 * HID + 4 * sl);
        float4 v1 = *reinterpret_cast<const float4*>(S + (size_t)n1 * HID + 4 * sl);
        float4 v2 = *reinterpret_cast<const float4*>(S + (size_t)n2 * HID + 4 * sl);
        float4 v3 = *reinterpret_cast<const float4*>(S + (size_t)n3 * HID + 4 * sl);
        a0 = fmaf(w0, v0.x, a0); a1 = fmaf(w0, v0.y, a1);
        a2 = fmaf(w0, v0.z, a2); a3 = fmaf(w0, v0.w, a3);
        b0 = fmaf(w1, v1.x, b0); b1 = fmaf(w1, v1.y, b1);
        b2 = fmaf(w1, v1.z, b2); b3 = fmaf(w1, v1.w, b3);
        a0 = fmaf(w2, v2.x, a0); a1 = fmaf(w2, v2.y, a1);
        a2 = fmaf(w2, v2.z, a2); a3 = fmaf(w2, v2.w, a3);
        b0 = fmaf(w3, v3.x, b0); b1 = fmaf(w3, v3.y, b1);
        b2 = fmaf(w3, v3.z, b2); b3 = fmaf(w3, v3.w, b3);
    }
    a0 += b0; a1 += b1; a2 += b2; a3 += b3;
    a0 += __shfl_xor_sync(0xffffffffu, a0, 16);
    a1 += __shfl_xor_sync(0xffffffffu, a1, 16);
    a2 += __shfl_xor_sync(0xffffffffu, a2, 16);
    a3 += __shfl_xor_sync(0xffffffffu, a3, 16);

    size_t rbase = (size_t)row * HID;

    if (lane < 16) {
        int c = 4 * sl;
        float4 bs = *reinterpret_cast<const float4*>(bias + c);
        float t0 = fmaxf(a0 + bs.x, 0.f), t1 = fmaxf(a1 + bs.y, 0.f);
        float t2 = fmaxf(a2 + bs.z, 0.f), t3 = fmaxf(a3 + bs.w, 0.f);
        if (MODE == 1) {
            float4 rv = *reinterpret_cast<const float4*>(resptr + (size_t)row * INF + c);
            t0 = (rv.x + t0) * 0.5f; t1 = (rv.y + t1) * 0.5f;
            t2 = (rv.z + t2) * 0.5f; t3 = (rv.w + t3) * 0.5f;
        }
        if (MODE == 2) {
            float4 rv = *reinterpret_cast<const float4*>(resptr + rbase + c);
            t0 = (rv.x + t0) * 0.5f; t1 = (rv.y + t1) * 0.5f;
            t2 = (rv.z + t2) * 0.5f; t3 = (rv.w + t3) * 0.5f;
        }
        if (MODE >= 1)
            *reinterpret_cast<float4*>(fbout + rbase + c) = make_float4(t0, t1, t2, t3);
        split_store4(t0, t1, t2, t3, ohi, olo, rbase + c);
    }
    {
        int c = 64 + 4 * lane;
        float4 sv = *reinterpret_cast<const float4*>(S + rbase + c);
        float4 bs = *reinterpret_cast<const float4*>(bias + c);
        float t0 = fmaxf(sv.x + bs.x, 0.f), t1 = fmaxf(sv.y + bs.y, 0.f);
        float t2 = fmaxf(sv.z + bs.z, 0.f), t3 = fmaxf(sv.w + bs.w, 0.f);
        if (MODE == 1) {
            float4 rv = *reinterpret_cast<const float4*>(resptr + (size_t)row * INF + c);
            t0 = (rv.x + t0) * 0.5f; t1 = (rv.y + t1) * 0.5f;
            t2 = (rv.z + t2) * 0.5f; t3 = (rv.w + t3) * 0.5f;
        }
        if (MODE == 2) {
            float4 rv = *reinterpret_cast<const float4*>(resptr + rbase + c);
            t0 = (rv.x + t0) * 0.5f; t1 = (rv.y + t1) * 0.5f;
            t2 = (rv.z + t2) * 0.5f; t3 = (rv.w + t3) * 0.5f;
        }
        if (MODE >= 1)
            *reinterpret_cast<float4*>(fbout + rbase + c) = make_float4(t0, t1, t2, t3);
        split_store4(t0, t1, t2, t3, ohi, olo, rbase + c);
    }
    gdc_launch();
}

// ---------------- fused tail (gc13 + feat @ W_out), PDL ----------------
__global__ __launch_bounds__(256) void tail_fused(const float* __restrict__ S,
                                                  const float* __restrict__ bias,
                                                  float* __restrict__ fb,
                                                  float* __restrict__ feat_out,
                                                  const float* __restrict__ W_out,
                                                  float* __restrict__ sup3,
                                                  const int* __restrict__ nidx,
                                                  const float* __restrict__ nval,
                                                  const int* __restrict__ ncnt)
{
    gdc_wait();
    gdc_launch();
    int row = (blockIdx.x * blockDim.x + threadIdx.x) >> 5;
    int lane = threadIdx.x & 31;
    int cnt = ncnt[row];
    const int* ni = nidx + (size_t)row * MAXN;
    const float* nv = nval + (size_t)row * MAXN;
    float acc0 = 0.f, acc1 = 0.f, e0 = 0.f, e1 = 0.f;
    for (int i = 0; i < cnt; i += 4) {
        int4   ji = *reinterpret_cast<const int4*>(ni + i);
        float4 ui = *reinterpret_cast<const float4*>(nv + i);
        const float* s0 = S + (size_t)ji.x * HID;
        const float* s1 = S + (size_t)ji.y * HID;
        const float* s2 = S + (size_t)ji.z * HID;
        const float* s3 = S + (size_t)ji.w * HID;
        acc0 = fmaf(ui.x, s0[lane], acc0);  acc1 = fmaf(ui.x, s0[lane + 32], acc1);
        e0   = fmaf(ui.y, s1[lane], e0);    e1   = fmaf(ui.y, s1[lane + 32], e1);
        acc0 = fmaf(ui.z, s2[lane], acc0);  acc1 = fmaf(ui.z, s2[lane + 32], acc1);
        e0   = fmaf(ui.w, s3[lane], e0);    e1   = fmaf(ui.w, s3[lane + 32], e1);
    }
    acc0 += e0; acc1 += e1;

    float w0s = 0.f, w1s = 0.f, w2s = 0.f;
    size_t rbase = (size_t)row * HID;
    #pragma unroll
    for (int j = 0; j < 6; j++) {
        int c = 32 * j + lane;
        float t = (j == 0) ? acc0 : (j == 1) ? acc1 : S[rbase + c];
        t += bias[c];
        t = fmaxf(t, 0.f);
        t = (fb[rbase + c] + t) * 0.5f;
        fb[rbase + c] = t;
        feat_out[rbase + c] = t;
        w0s = fmaf(t, W_out[c * 3 + 0], w0s);
        w1s = fmaf(t, W_out[c * 3 + 1], w1s);
        w2s = fmaf(t, W_out[c * 3 + 2], w2s);
    }
    #pragma unroll
    for (int d = 16; d; d >>= 1) {
        w0s += __shfl_xor_sync(0xffffffffu, w0s, d);
        w1s += __shfl_xor_sync(0xffffffffu, w1s, d);
        w2s += __shfl_xor_sync(0xffffffffu, w2s, d);
    }
    if (lane == 0) {
        sup3[row * 3 + 0] = w0s;
        sup3[row * 3 + 1] = w1s;
        sup3[row * 3 + 2] = w2s;
    }
}

// ---------------- coords, PDL ----------------
__global__ __launch_bounds__(256) void agg_coords(const float* __restrict__ S,
                                                  const float* __restrict__ bias,
                                                  float* __restrict__ out,
                                                  const int* __restrict__ nidx,
                                                  const float* __restrict__ nval,
                                                  const int* __restrict__ ncnt)
{
    gdc_wait();
    int warp = (blockIdx.x * blockDim.x + threadIdx.x) >> 5;
    int lane = threadIdx.x & 31;
    int cnt = ncnt[warp];
    const int* ni = nidx + (size_t)warp * MAXN;
    const float* nv = nval + (size_t)warp * MAXN;
    float acc0 = 0.f;
    for (int i = 0; i < cnt; i++) {
        if (lane < 2) acc0 = fmaf(nv[i], S[(size_t)ni[i] * 3 + lane], acc0);
    }
    if (lane < 3) {
        float t = (lane < 2) ? acc0 : S[(size_t)warp * 3 + lane];
        out[(size_t)warp * 3 + lane] = t + bias[lane];
    }
}

// ---------------- host PDL launcher ----------------
template <typename F, typename... Args>
static inline void pdl(F fn, dim3 g, dim3 b, size_t sm, Args... args)
{
    cudaLaunchConfig_t cfg = {};
    cfg.gridDim = g; cfg.blockDim = b; cfg.dynamicSmemBytes = sm; cfg.stream = 0;
    cudaLaunchAttribute at;
    at.id = cudaLaunchAttributeProgrammaticStreamSerialization;
    at.val.programmaticStreamSerializationAllowed = 1;
    cfg.attrs = &at; cfg.numAttrs = 1;
    cudaLaunchKernelEx(&cfg, fn, args...);
}

extern "C" void kernel_launch(void* const* d_in, const int* in_sizes, int n_in,
                              void* d_out, int out_size)
{
    const float* features = (const float*)d_in[0];
    const float* adj      = (const float*)d_in[1];
    const float* W1       = (const float*)d_in[2];
    const float* b1       = (const float*)d_in[3];
    const float* W_mid    = (const float*)d_in[4];
    const float* b_mid    = (const float*)d_in[5];
    const float* W_out    = (const float*)d_in[6];
    const float* b_out    = (const float*)d_in[7];
    float* out = (float*)d_out;
    float* coords   = out;
    float* feat_out = out + NN * 3;

    float *sa, *sbuf, *fb, *sup3, *nval;
    __nv_bfloat16 *xhi, *xlo, *whi, *wlo;
    int *nidx, *ncnt;
    cudaGetSymbolAddress((void**)&sa,   g_supA);
    cudaGetSymbolAddress((void**)&sbuf, g_supB);
    cudaGetSymbolAddress((void**)&fb,   g_featbuf);
    cudaGetSymbolAddress((void**)&sup3, g_sup3);
    cudaGetSymbolAddress((void**)&xhi,  g_xhi);
    cudaGetSymbolAddress((void**)&xlo,  g_xlo);
    cudaGetSymbolAddress((void**)&whi,  g_wthi);
    cudaGetSymbolAddress((void**)&wlo,  g_wtlo);
    cudaGetSymbolAddress((void**)&nidx, g_nidx);
    cudaGetSymbolAddress((void**)&nval, g_nval);
    cudaGetSymbolAddress((void**)&ncnt, g_ncnt);

    cudaFuncSetAttribute(gemm_os, cudaFuncAttributeMaxDynamicSharedMemorySize, OS_SMEM);
    cudaFuncSetAttribute(gemm_full, cudaFuncAttributeMaxDynamicSharedMemorySize, GF_SMEM);

    // R7/R10-proven ordering: csr FIRST (its 268MB sweep evicts L2), converts after.
    build_csr<<<NN / 8, 256>>>(adj, nidx, nval, ncnt);
    pdl(convert_weights, dim3((WT_TOTAL + 255) / 256), dim3(256), (size_t)0, W1, W_mid, whi, wlo);
    pdl(convert_features, dim3((NN * INF + 255) / 256), dim3(256), (size_t)0, features, xhi, xlo);

    auto woff = [](int i) { return (size_t)192 * 256 + (size_t)i * 192 * 192; };

    pdl(gemm_os, dim3(NN / 64), dim3(512), (size_t)OS_SMEM,
        (const __nv_bfloat16*)xhi, (const __nv_bfloat16*)xlo,
        (const __nv_bfloat16*)whi, (const __nv_bfloat16*)wlo, sa);

    pdl(agg2<0>, dim3(NN / 8), dim3(256), (size_t)0,
        (const float*)sa, b1, (const float*)nullptr, (float*)nullptr,
        xhi, xlo, (const int*)nidx, (const float*)nval, (const int*)ncnt);
    pdl(gemm_full, dim3(NN / 64), dim3(512), (size_t)GF_SMEM,
        (const __nv_bfloat16*)xhi, (const __nv_bfloat16*)xlo,
        (const __nv_bfloat16*)(whi + woff(0)), (const __nv_bfloat16*)(wlo + woff(0)), sbuf);
    pdl(agg2<1>, dim3(NN / 8), dim3(256), (size_t)0,
        (const float*)sbuf, (const float*)(b_mid + 0), features, fb,
        xhi, xlo, (const int*)nidx, (const float*)nval, (const int*)ncnt);
    pdl(gemm_full, dim3(NN / 64), dim3(512), (size_t)GF_SMEM,
        (const __nv_bfloat16*)xhi, (const __nv_bfloat16*)xlo,
        (const __nv_bfloat16*)(whi + woff(1)), (const __nv_bfloat16*)(wlo + woff(1)), sa);

    float* cur = sa; float* nxt = sbuf;
    for (int p = 0; p < 5; p++) {
        int bi = 1 + 2 * p;
        pdl(agg2<0>, dim3(NN / 8), dim3(256), (size_t)0,
            (const float*)cur, (const float*)(b_mid + (size_t)bi * HID),
            (const float*)nullptr, (float*)nullptr,
            xhi, xlo, (const int*)nidx, (const float*)nval, (const int*)ncnt);
        pdl(gemm_full, dim3(NN / 64), dim3(512), (size_t)GF_SMEM,
            (const __nv_bfloat16*)xhi, (const __nv_bfloat16*)xlo,
            (const __nv_bfloat16*)(whi + woff(bi + 1)), (const __nv_bfloat16*)(wlo + woff(bi + 1)), nxt);
        { float* t = cur; cur = nxt; nxt = t; }
        pdl(agg2<2>, dim3(NN / 8), dim3(256), (size_t)0,
            (const float*)cur, (const float*)(b_mid + (size_t)(bi + 1) * HID),
            (const float*)fb, fb,
            xhi, xlo, (const int*)nidx, (const float*)nval, (const int*)ncnt);
        pdl(gemm_full, dim3(NN / 64), dim3(512), (size_t)GF_SMEM,
            (const __nv_bfloat16*)xhi, (const __nv_bfloat16*)xlo,
            (const __nv_bfloat16*)(whi + woff(bi + 2)), (const __nv_bfloat16*)(wlo + woff(bi + 2)), nxt);
        { float* t = cur; cur = nxt; nxt = t; }
    }

    pdl(tail_fused, dim3(NN / 8), dim3(256), (size_t)0,
        (const float*)cur, (const float*)(b_mid + (size_t)11 * HID), fb, feat_out,
        W_out, sup3, (const int*)nidx, (const float*)nval, (const int*)ncnt);
    pdl(agg_coords, dim3(NN / 8), dim3(256), (size_t)0,
        (const float*)sup3, b_out, coords,
        (const int*)nidx, (const float*)nval, (const int*)ncnt);
}